// round 1
// baseline (speedup 1.0000x reference)
#include <cuda_runtime.h>
#include <cstdint>

// ---------------------------------------------------------------------------
// Problem constants
// ---------------------------------------------------------------------------
#define NN     100000     // nodes
#define NE     600000     // edges
#define NCEN   512        // center_mol_idx
#define NMOLN  20000      // non_molecule_node_ids
#define NRELS  50
#define D      128        // emb = hidden = 128
#define NMOT   85

// output layout: edge_class[NE,50] | motif[NCEN,85] | node_class[NMOLN,15] | bin[NN,1]
#define OFF_MOTIF (NE * 50)                    // 30,000,000
#define OFF_NODE  (OFF_MOTIF + NCEN * NMOT)    // 30,043,520
#define OFF_BIN   (OFF_NODE + NMOLN * 15)      // 30,343,520

// ---------------------------------------------------------------------------
// Device scratch (no allocations allowed)
// ---------------------------------------------------------------------------
__device__ float g_xn  [NN * D];     // normalized gathered node embeddings
__device__ float g_x0  [NN * D];     // after lin+relu
__device__ float g_x1  [NN * D];     // after GINE1
__device__ float g_x2  [NN * D];     // after GINE2
__device__ float g_agg [NN * D];     // segment-sum buffer
__device__ float g_en  [NRELS * D];  // normalized rel embeddings
__device__ float g_elin[NRELS * D];  // rel after lin+relu
__device__ float g_proj[NN * 116];   // packed projection: P1(50)|P2(50)|nodec(15)|bin(1)
__device__ float g_Wcat[D * 116];
__device__ float g_bcat[116];

// ---------------------------------------------------------------------------
// f32x2 packed-FMA helpers (Blackwell packed fp32, 2x FFMA throughput)
// ---------------------------------------------------------------------------
__device__ __forceinline__ unsigned long long pk2(float lo, float hi) {
    unsigned long long r;
    asm("mov.b64 %0, {%1,%2};" : "=l"(r) : "f"(lo), "f"(hi));
    return r;
}
__device__ __forceinline__ void upk2(unsigned long long v, float& lo, float& hi) {
    asm("mov.b64 {%0,%1}, %2;" : "=f"(lo), "=f"(hi) : "l"(v));
}
__device__ __forceinline__ void fma2(unsigned long long& acc, unsigned long long a,
                                     unsigned long long b) {
    asm("fma.rn.f32x2 %0, %1, %2, %0;" : "+l"(acc) : "l"(a), "l"(b));
}

// ---------------------------------------------------------------------------
// Gather + L2-normalize rows (one warp per row). ids==nullptr -> identity.
// ---------------------------------------------------------------------------
__global__ void norm_gather_k(const float* __restrict__ table,
                              const int* __restrict__ ids, int n,
                              float* __restrict__ out) {
    int w = (blockIdx.x * blockDim.x + threadIdx.x) >> 5;
    if (w >= n) return;
    int lane = threadIdx.x & 31;
    int g = ids ? ids[w] : w;
    float4 v = reinterpret_cast<const float4*>(table + (size_t)g * D)[lane];
    float ss = v.x * v.x + v.y * v.y + v.z * v.z + v.w * v.w;
#pragma unroll
    for (int o = 16; o; o >>= 1) ss += __shfl_xor_sync(0xffffffffu, ss, o);
    float nr = sqrtf(ss);
    float inv = 1.0f / fmaxf(nr, 1e-12f);
    v.x *= inv; v.y *= inv; v.z *= inv; v.w *= inv;
    reinterpret_cast<float4*>(out + (size_t)w * D)[lane] = v;
}

// ---------------------------------------------------------------------------
// Tiled GEMM: Y[r,c] = act( sum_k A[r,k] * W[k,c] + b[c] )
// K = 128 fixed, C <= 128 template. 256 threads, 64-row tiles.
// AMODE: 0 = A1 ; 1 = A1 + A2 (GINE pre-add) ; 2 = A1[ridx[r]] (gather rows)
// Inner loop uses fma.rn.f32x2 (2 cols per op).
// ---------------------------------------------------------------------------
template <int C, bool RELU, int AMODE>
__global__ __launch_bounds__(256)
void gemm_k(const float* __restrict__ A1, const float* __restrict__ A2,
            const int* __restrict__ ridx, int nrows,
            const float* __restrict__ W, const float* __restrict__ bias,
            float* __restrict__ Y) {
    constexpr int CP = (C + 1) & ~1;  // even-padded col count
    extern __shared__ float sm[];
    float* sA = sm;                // 64*128
    float* sW = sm + 64 * 128;     // 128*CP
    float* sB = sW + 128 * CP;     // CP

    const int tid = threadIdx.x;
    for (int i = tid; i < 128 * CP; i += 256) {
        int k = i / CP, c = i - k * CP;
        sW[i] = (c < C) ? W[k * C + c] : 0.0f;
    }
    if (tid < CP) sB[tid] = (tid < C) ? bias[tid] : 0.0f;

    const int r0 = blockIdx.x * 64;
    for (int i = tid; i < 64 * 128; i += 256) {
        int r = i >> 7, k = i & 127;
        int gr = r0 + r;
        float v = 0.0f;
        if (gr < nrows) {
            if (AMODE == 0)      v = A1[(size_t)gr * D + k];
            else if (AMODE == 1) v = A1[(size_t)gr * D + k] + A2[(size_t)gr * D + k];
            else                 v = A1[(size_t)ridx[gr] * D + k];
        }
        sA[i] = v;
    }
    __syncthreads();

    const int tx = tid & 31, ty = tid >> 5;
    const int c0 = tx * 4;
    unsigned long long acc[8][2];
#pragma unroll
    for (int r = 0; r < 8; r++) { acc[r][0] = 0ull; acc[r][1] = 0ull; }

    const unsigned long long* sW2 = reinterpret_cast<const unsigned long long*>(sW);
    const float* sAr = sA + ty * 8 * 128;

#pragma unroll 4
    for (int k = 0; k < 128; k++) {
        unsigned long long w0 = sW2[(k * CP + c0) >> 1];
        unsigned long long w1 = sW2[(k * CP + c0 + 2) >> 1];
#pragma unroll
        for (int r = 0; r < 8; r++) {
            float a = sAr[r * 128 + k];
            unsigned long long a2 = pk2(a, a);
            fma2(acc[r][0], a2, w0);
            fma2(acc[r][1], a2, w1);
        }
    }

#pragma unroll
    for (int r = 0; r < 8; r++) {
        int row = r0 + ty * 8 + r;
        if (row >= nrows) continue;
        float f[4];
        upk2(acc[r][0], f[0], f[1]);
        upk2(acc[r][1], f[2], f[3]);
        float* yr = Y + (size_t)row * C;
#pragma unroll
        for (int j = 0; j < 4; j++) {
            int c = c0 + j;
            if (c < C) {
                float v = f[j] + sB[c];
                if (RELU) v = fmaxf(v, 0.0f);
                yr[c] = v;
            }
        }
    }
}

// ---------------------------------------------------------------------------
// Message pass: agg[dst] += relu(X[src] + Elin[rel]).  One warp per edge.
// ---------------------------------------------------------------------------
__global__ void msg_k(const float* __restrict__ X, const float* __restrict__ Elin,
                      const int* __restrict__ src, const int* __restrict__ dst,
                      const int* __restrict__ rel, float* __restrict__ agg, int nE) {
    int w = (blockIdx.x * blockDim.x + threadIdx.x) >> 5;
    if (w >= nE) return;
    int lane = threadIdx.x & 31;
    int s = __ldg(src + w), d = __ldg(dst + w), r = __ldg(rel + w);
    float4 a = reinterpret_cast<const float4*>(X + (size_t)s * D)[lane];
    float4 b = reinterpret_cast<const float4*>(Elin + (size_t)r * D)[lane];
    float4 m;
    m.x = fmaxf(a.x + b.x, 0.0f);
    m.y = fmaxf(a.y + b.y, 0.0f);
    m.z = fmaxf(a.z + b.z, 0.0f);
    m.w = fmaxf(a.w + b.w, 0.0f);
    float* p = agg + (size_t)d * D + lane * 4;
    atomicAdd(p + 0, m.x);
    atomicAdd(p + 1, m.y);
    atomicAdd(p + 2, m.z);
    atomicAdd(p + 3, m.w);
}

__global__ void zero_k(float4* __restrict__ p, int n4) {
    int i = blockIdx.x * blockDim.x + threadIdx.x;
    if (i < n4) p[i] = make_float4(0.f, 0.f, 0.f, 0.f);
}

// Pack [edge_W_src | edge_W_dst | nodec_W | bin_W] -> Wcat[128,116], biases -> bcat
__global__ void pack_k(const float* __restrict__ eW, const float* __restrict__ ncW,
                       const float* __restrict__ bW, const float* __restrict__ eb,
                       const float* __restrict__ ncb, const float* __restrict__ bb,
                       float* __restrict__ Wcat, float* __restrict__ bcat) {
    int i = blockIdx.x * blockDim.x + threadIdx.x;
    if (i < 128 * 116) {
        int k = i / 116, c = i - k * 116;
        float v;
        if (c < 50)       v = eW[k * 50 + c];
        else if (c < 100) v = eW[(128 + k) * 50 + (c - 50)];
        else if (c < 115) v = ncW[k * 15 + (c - 100)];
        else              v = bW[k];
        Wcat[i] = v;
    }
    if (i < 116) {
        float v;
        if (i < 50)       v = eb[i];         // edge bias folded into P1 only
        else if (i < 100) v = 0.0f;
        else if (i < 115) v = ncb[i - 100];
        else              v = bb[0];
        bcat[i] = v;
    }
}

// edge_class[e,c] = P1[src[e],c] + P2[dst[e],c]   (bias already in P1)
__global__ void edge_out_k(const float* __restrict__ proj, const int* __restrict__ src,
                           const int* __restrict__ dst, float* __restrict__ out) {
    int i = blockIdx.x * blockDim.x + threadIdx.x;   // NE*25 float2 elems
    if (i >= NE * 25) return;
    int e = i / 25, j = i - e * 25;
    int c = j * 2;
    int s = __ldg(src + e), d = __ldg(dst + e);
    float2 p1 = *reinterpret_cast<const float2*>(proj + (size_t)s * 116 + c);
    float2 p2 = *reinterpret_cast<const float2*>(proj + (size_t)d * 116 + 50 + c);
    *reinterpret_cast<float2*>(out + (size_t)e * 50 + c) =
        make_float2(p1.x + p2.x, p1.y + p2.y);
}

__global__ void node_out_k(const float* __restrict__ proj, const int* __restrict__ ids,
                           float* __restrict__ out) {
    int i = blockIdx.x * blockDim.x + threadIdx.x;
    if (i >= NMOLN * 15) return;
    int m = i / 15, c = i - m * 15;
    out[i] = proj[(size_t)__ldg(ids + m) * 116 + 100 + c];
}

__global__ void bin_out_k(const float* __restrict__ proj, float* __restrict__ out) {
    int n = blockIdx.x * blockDim.x + threadIdx.x;
    if (n < NN) out[n] = proj[(size_t)n * 116 + 115];
}

// ---------------------------------------------------------------------------
// Launch
// ---------------------------------------------------------------------------
static inline int cdiv(long long a, long long b) { return (int)((a + b - 1) / b); }

static constexpr int smem_bytes(int C) {
    int CP = (C + 1) & ~1;
    return (64 * 128 + 128 * CP + CP) * 4;
}

extern "C" void kernel_launch(void* const* d_in, const int* in_sizes, int n_in,
                              void* d_out, int out_size) {
    const int*   node_ids = (const int*)d_in[0];
    const int*   rel_ids  = (const int*)d_in[1];
    const int*   center   = (const int*)d_in[2];
    const int*   nonmol   = (const int*)d_in[3];
    const int*   eidx     = (const int*)d_in[4];
    const float* node_emb = (const float*)d_in[5];
    const float* rel_emb  = (const float*)d_in[6];
    const float* lin_W    = (const float*)d_in[7];
    const float* lin_b    = (const float*)d_in[8];
    const float* W1       = (const float*)d_in[9];
    const float* b1       = (const float*)d_in[10];
    const float* W2       = (const float*)d_in[11];
    const float* b2       = (const float*)d_in[12];
    const float* edge_W   = (const float*)d_in[13];
    const float* edge_b   = (const float*)d_in[14];
    const float* motif_W  = (const float*)d_in[15];
    const float* motif_b  = (const float*)d_in[16];
    const float* nodec_W  = (const float*)d_in[17];
    const float* nodec_b  = (const float*)d_in[18];
    const float* bin_W    = (const float*)d_in[19];
    const float* bin_b    = (const float*)d_in[20];
    const int* src = eidx;
    const int* dst = eidx + NE;
    float* out = (float*)d_out;

    float *xn, *x0, *x1, *x2, *agg, *en, *elin, *proj, *Wcat, *bcat;
    cudaGetSymbolAddress((void**)&xn,   g_xn);
    cudaGetSymbolAddress((void**)&x0,   g_x0);
    cudaGetSymbolAddress((void**)&x1,   g_x1);
    cudaGetSymbolAddress((void**)&x2,   g_x2);
    cudaGetSymbolAddress((void**)&agg,  g_agg);
    cudaGetSymbolAddress((void**)&en,   g_en);
    cudaGetSymbolAddress((void**)&elin, g_elin);
    cudaGetSymbolAddress((void**)&proj, g_proj);
    cudaGetSymbolAddress((void**)&Wcat, g_Wcat);
    cudaGetSymbolAddress((void**)&bcat, g_bcat);

    constexpr int SM128 = smem_bytes(128);
    constexpr int SM116 = smem_bytes(116);
    constexpr int SM85  = smem_bytes(85);
    cudaFuncSetAttribute(gemm_k<128, true,  0>, cudaFuncAttributeMaxDynamicSharedMemorySize, SM128);
    cudaFuncSetAttribute(gemm_k<128, true,  1>, cudaFuncAttributeMaxDynamicSharedMemorySize, SM128);
    cudaFuncSetAttribute(gemm_k<128, false, 1>, cudaFuncAttributeMaxDynamicSharedMemorySize, SM128);
    cudaFuncSetAttribute(gemm_k<116, false, 0>, cudaFuncAttributeMaxDynamicSharedMemorySize, SM116);
    cudaFuncSetAttribute(gemm_k<85,  false, 2>, cudaFuncAttributeMaxDynamicSharedMemorySize, SM85);

    const int n4 = NN * D / 4;

    // 1) pack output-head weights
    pack_k<<<cdiv(128 * 116, 256), 256>>>(edge_W, nodec_W, bin_W, edge_b, nodec_b, bin_b,
                                          Wcat, bcat);
    // 2) rel features: normalize 50 rows, then lin+relu -> elin[50,128]
    norm_gather_k<<<cdiv((long long)NRELS * 32, 256), 256>>>(rel_emb, nullptr, NRELS, en);
    gemm_k<128, true, 0><<<1, 256, SM128>>>(en, nullptr, nullptr, NRELS, lin_W, lin_b, elin);
    // 3) node features: gather+normalize, then lin+relu -> x0
    norm_gather_k<<<cdiv((long long)NN * 32, 256), 256>>>(node_emb, node_ids, NN, xn);
    gemm_k<128, true, 0><<<cdiv(NN, 64), 256, SM128>>>(xn, nullptr, nullptr, NN,
                                                       lin_W, lin_b, x0);
    // 4) GINE layer 1
    zero_k<<<cdiv(n4, 256), 256>>>((float4*)agg, n4);
    msg_k<<<cdiv((long long)NE * 32, 256), 256>>>(x0, elin, src, dst, rel_ids, agg, NE);
    gemm_k<128, true, 1><<<cdiv(NN, 64), 256, SM128>>>(x0, agg, nullptr, NN, W1, b1, x1);
    // 5) GINE layer 2 (no relu)
    zero_k<<<cdiv(n4, 256), 256>>>((float4*)agg, n4);
    msg_k<<<cdiv((long long)NE * 32, 256), 256>>>(x1, elin, src, dst, rel_ids, agg, NE);
    gemm_k<128, false, 1><<<cdiv(NN, 64), 256, SM128>>>(x1, agg, nullptr, NN, W2, b2, x2);
    // 6) fused per-node projection: P1|P2|nodec|bin
    gemm_k<116, false, 0><<<cdiv(NN, 64), 256, SM116>>>(x2, nullptr, nullptr, NN,
                                                        Wcat, bcat, proj);
    // 7) outputs
    edge_out_k<<<cdiv((long long)NE * 25, 256), 256>>>(proj, src, dst, out);
    gemm_k<85, false, 2><<<cdiv(NCEN, 64), 256, SM85>>>(x2, nullptr, center, NCEN,
                                                        motif_W, motif_b, out + OFF_MOTIF);
    node_out_k<<<cdiv((long long)NMOLN * 15, 256), 256>>>(proj, nonmol, out + OFF_NODE);
    bin_out_k<<<cdiv(NN, 256), 256>>>(proj, out + OFF_BIN);
}

// round 2
// speedup vs baseline: 1.1500x; 1.1500x over previous
#include <cuda_runtime.h>
#include <cstdint>

// ---------------------------------------------------------------------------
// Problem constants
// ---------------------------------------------------------------------------
#define NN     100000     // nodes
#define NE     600000     // edges
#define NCEN   512        // center_mol_idx
#define NMOLN  20000      // non_molecule_node_ids
#define NRELS  50
#define D      128        // emb = hidden = 128
#define NMOT   85

// output layout: edge_class[NE,50] | motif[NCEN,85] | node_class[NMOLN,15] | bin[NN,1]
#define OFF_MOTIF (NE * 50)
#define OFF_NODE  (OFF_MOTIF + NCEN * NMOT)
#define OFF_BIN   (OFF_NODE + NMOLN * 15)

// ---------------------------------------------------------------------------
// Device scratch (no allocations allowed)
// ---------------------------------------------------------------------------
__device__ float g_x0  [NN * D];     // after lin+relu
__device__ float g_x1  [NN * D];     // after GINE1
__device__ float g_x2  [NN * D];     // after GINE2
__device__ float g_agg [NN * D];     // segment-sum buffer
__device__ float g_en  [NRELS * D];  // normalized rel embeddings
__device__ float g_elin[NRELS * D];  // rel after lin+relu
__device__ float g_proj[NN * 116];   // packed projection: P1(50)|P2(50)|nodec(15)|bin(1)
__device__ float g_Wcat[D * 116];
__device__ float g_bcat[116];

// ---------------------------------------------------------------------------
// f32x2 packed-FMA helpers (Blackwell packed fp32, 2x FFMA throughput)
// ---------------------------------------------------------------------------
__device__ __forceinline__ unsigned long long pk2(float lo, float hi) {
    unsigned long long r;
    asm("mov.b64 %0, {%1,%2};" : "=l"(r) : "f"(lo), "f"(hi));
    return r;
}
__device__ __forceinline__ void upk2(unsigned long long v, float& lo, float& hi) {
    asm("mov.b64 {%0,%1}, %2;" : "=f"(lo), "=f"(hi) : "l"(v));
}
__device__ __forceinline__ void fma2(unsigned long long& acc, unsigned long long a,
                                     unsigned long long b) {
    asm("fma.rn.f32x2 %0, %1, %2, %0;" : "+l"(acc) : "l"(a), "l"(b));
}

// ---------------------------------------------------------------------------
// Gather + L2-normalize rows (one warp per row). ids==nullptr -> identity.
// (only used for the 50 relation rows now)
// ---------------------------------------------------------------------------
__global__ void norm_gather_k(const float* __restrict__ table,
                              const int* __restrict__ ids, int n,
                              float* __restrict__ out) {
    int w = (blockIdx.x * blockDim.x + threadIdx.x) >> 5;
    if (w >= n) return;
    int lane = threadIdx.x & 31;
    int g = ids ? ids[w] : w;
    float4 v = reinterpret_cast<const float4*>(table + (size_t)g * D)[lane];
    float ss = v.x * v.x + v.y * v.y + v.z * v.z + v.w * v.w;
#pragma unroll
    for (int o = 16; o; o >>= 1) ss += __shfl_xor_sync(0xffffffffu, ss, o);
    float inv = 1.0f / fmaxf(sqrtf(ss), 1e-12f);
    v.x *= inv; v.y *= inv; v.z *= inv; v.w *= inv;
    reinterpret_cast<float4*>(out + (size_t)w * D)[lane] = v;
}

// ---------------------------------------------------------------------------
// Tiled GEMM: Y[r,c] = act( sum_k A[r,k] * W[k,c] + b[c] )
// K = 128 fixed, C <= 128 template. 256 threads, 64-row tiles.
// AMODE: 0 = A1 ; 1 = A1 + A2 (GINE pre-add) ; 2 = A1[ridx[r]] (gather rows)
//        3 = l2normalize(A1[ridx[r]]) (fused gather + normalize)
// Inner loop uses fma.rn.f32x2 (2 cols per op).
// ---------------------------------------------------------------------------
template <int C, bool RELU, int AMODE>
__global__ __launch_bounds__(256)
void gemm_k(const float* __restrict__ A1, const float* __restrict__ A2,
            const int* __restrict__ ridx, int nrows,
            const float* __restrict__ W, const float* __restrict__ bias,
            float* __restrict__ Y) {
    constexpr int CP = (C + 1) & ~1;  // even-padded col count
    extern __shared__ float sm[];
    float* sA   = sm;                 // 64*128
    float* sW   = sm + 64 * 128;      // 128*CP
    float* sB   = sW + 128 * CP;      // CP
    float* sInv = sB + CP;            // 64
    int*   sIdx = (int*)(sInv + 64);  // 64

    const int tid = threadIdx.x;
    for (int i = tid; i < 128 * CP; i += 256) {
        int k = i / CP, c = i - k * CP;
        sW[i] = (c < C) ? W[k * C + c] : 0.0f;
    }
    if (tid < CP) sB[tid] = (tid < C) ? bias[tid] : 0.0f;

    const int r0 = blockIdx.x * 64;
    if (AMODE >= 2) {
        if (tid < 64) {
            int gr = r0 + tid;
            sIdx[tid] = (gr < nrows) ? ridx[gr] : 0;
        }
        __syncthreads();
    }
    for (int i = tid; i < 64 * 128; i += 256) {
        int r = i >> 7, k = i & 127;
        int gr = r0 + r;
        float v = 0.0f;
        if (gr < nrows) {
            if (AMODE == 0)      v = A1[(size_t)gr * D + k];
            else if (AMODE == 1) v = A1[(size_t)gr * D + k] + A2[(size_t)gr * D + k];
            else                 v = A1[(size_t)sIdx[r] * D + k];
        }
        sA[i] = v;
    }
    __syncthreads();

    if (AMODE == 3) {
        // per-row L2 norm: warp w handles rows w*8..w*8+7
        int lane = tid & 31, w = tid >> 5;
#pragma unroll
        for (int rr = 0; rr < 8; rr++) {
            int r = w * 8 + rr;
            float s = 0.0f;
#pragma unroll
            for (int j = 0; j < 4; j++) {
                float a = sA[r * 128 + lane + 32 * j];
                s += a * a;
            }
#pragma unroll
            for (int o = 16; o; o >>= 1) s += __shfl_xor_sync(0xffffffffu, s, o);
            if (lane == 0) sInv[r] = 1.0f / fmaxf(sqrtf(s), 1e-12f);
        }
        __syncthreads();
        for (int i = tid; i < 64 * 128; i += 256) sA[i] *= sInv[i >> 7];
        __syncthreads();
    }

    const int tx = tid & 31, ty = tid >> 5;
    const int c0 = tx * 4;
    unsigned long long acc[8][2];
#pragma unroll
    for (int r = 0; r < 8; r++) { acc[r][0] = 0ull; acc[r][1] = 0ull; }

    const unsigned long long* sW2 = reinterpret_cast<const unsigned long long*>(sW);
    const float* sAr = sA + ty * 8 * 128;

#pragma unroll 4
    for (int k = 0; k < 128; k++) {
        unsigned long long w0 = sW2[(k * CP + c0) >> 1];
        unsigned long long w1 = sW2[(k * CP + c0 + 2) >> 1];
#pragma unroll
        for (int r = 0; r < 8; r++) {
            float a = sAr[r * 128 + k];
            unsigned long long a2 = pk2(a, a);
            fma2(acc[r][0], a2, w0);
            fma2(acc[r][1], a2, w1);
        }
    }

#pragma unroll
    for (int r = 0; r < 8; r++) {
        int row = r0 + ty * 8 + r;
        if (row >= nrows) continue;
        float f[4];
        upk2(acc[r][0], f[0], f[1]);
        upk2(acc[r][1], f[2], f[3]);
        float* yr = Y + (size_t)row * C;
#pragma unroll
        for (int j = 0; j < 4; j++) {
            int c = c0 + j;
            if (c < C) {
                float v = f[j] + sB[c];
                if (RELU) v = fmaxf(v, 0.0f);
                yr[c] = v;
            }
        }
    }
}

// ---------------------------------------------------------------------------
// Message pass: agg[dst] += relu(X[src] + Elin[rel]).  One warp per edge.
// Vectorized RED: atomicAdd(float4*) -> RED.ADD.v4 (4x fewer L2 atomic ops).
// ---------------------------------------------------------------------------
__global__ void msg_k(const float* __restrict__ X, const float* __restrict__ Elin,
                      const int* __restrict__ src, const int* __restrict__ dst,
                      const int* __restrict__ rel, float* __restrict__ agg, int nE) {
    int w = (blockIdx.x * blockDim.x + threadIdx.x) >> 5;
    if (w >= nE) return;
    int lane = threadIdx.x & 31;
    int s = __ldg(src + w), d = __ldg(dst + w), r = __ldg(rel + w);
    float4 a = reinterpret_cast<const float4*>(X + (size_t)s * D)[lane];
    float4 b = reinterpret_cast<const float4*>(Elin + (size_t)r * D)[lane];
    float4 m;
    m.x = fmaxf(a.x + b.x, 0.0f);
    m.y = fmaxf(a.y + b.y, 0.0f);
    m.z = fmaxf(a.z + b.z, 0.0f);
    m.w = fmaxf(a.w + b.w, 0.0f);
    atomicAdd(reinterpret_cast<float4*>(agg + (size_t)d * D) + lane, m);
}

__global__ void zero_k(float4* __restrict__ p, int n4) {
    int i = blockIdx.x * blockDim.x + threadIdx.x;
    if (i < n4) p[i] = make_float4(0.f, 0.f, 0.f, 0.f);
}

// Pack [edge_W_src | edge_W_dst | nodec_W | bin_W] -> Wcat[128,116], biases -> bcat
__global__ void pack_k(const float* __restrict__ eW, const float* __restrict__ ncW,
                       const float* __restrict__ bW, const float* __restrict__ eb,
                       const float* __restrict__ ncb, const float* __restrict__ bb,
                       float* __restrict__ Wcat, float* __restrict__ bcat) {
    int i = blockIdx.x * blockDim.x + threadIdx.x;
    if (i < 128 * 116) {
        int k = i / 116, c = i - k * 116;
        float v;
        if (c < 50)       v = eW[k * 50 + c];
        else if (c < 100) v = eW[(128 + k) * 50 + (c - 50)];
        else if (c < 115) v = ncW[k * 15 + (c - 100)];
        else              v = bW[k];
        Wcat[i] = v;
    }
    if (i < 116) {
        float v;
        if (i < 50)       v = eb[i];         // edge bias folded into P1 only
        else if (i < 100) v = 0.0f;
        else if (i < 115) v = ncb[i - 100];
        else              v = bb[0];
        bcat[i] = v;
    }
}

// edge_class[e,c] = P1[src[e],c] + P2[dst[e],c]   (bias already in P1)
__global__ void edge_out_k(const float* __restrict__ proj, const int* __restrict__ src,
                           const int* __restrict__ dst, float* __restrict__ out) {
    int i = blockIdx.x * blockDim.x + threadIdx.x;   // NE*25 float2 elems
    if (i >= NE * 25) return;
    int e = i / 25, j = i - e * 25;
    int c = j * 2;
    int s = __ldg(src + e), d = __ldg(dst + e);
    float2 p1 = *reinterpret_cast<const float2*>(proj + (size_t)s * 116 + c);
    float2 p2 = *reinterpret_cast<const float2*>(proj + (size_t)d * 116 + 50 + c);
    *reinterpret_cast<float2*>(out + (size_t)e * 50 + c) =
        make_float2(p1.x + p2.x, p1.y + p2.y);
}

__global__ void node_out_k(const float* __restrict__ proj, const int* __restrict__ ids,
                           float* __restrict__ out) {
    int i = blockIdx.x * blockDim.x + threadIdx.x;
    if (i >= NMOLN * 15) return;
    int m = i / 15, c = i - m * 15;
    out[i] = proj[(size_t)__ldg(ids + m) * 116 + 100 + c];
}

__global__ void bin_out_k(const float* __restrict__ proj, float* __restrict__ out) {
    int n = blockIdx.x * blockDim.x + threadIdx.x;
    if (n < NN) out[n] = proj[(size_t)n * 116 + 115];
}

// ---------------------------------------------------------------------------
// Launch
// ---------------------------------------------------------------------------
static inline int cdiv(long long a, long long b) { return (int)((a + b - 1) / b); }

static constexpr int smem_bytes(int C) {
    int CP = (C + 1) & ~1;
    return (64 * 128 + 128 * CP + CP + 64 + 64) * 4;
}

extern "C" void kernel_launch(void* const* d_in, const int* in_sizes, int n_in,
                              void* d_out, int out_size) {
    const int*   node_ids = (const int*)d_in[0];
    const int*   rel_ids  = (const int*)d_in[1];
    const int*   center   = (const int*)d_in[2];
    const int*   nonmol   = (const int*)d_in[3];
    const int*   eidx     = (const int*)d_in[4];
    const float* node_emb = (const float*)d_in[5];
    const float* rel_emb  = (const float*)d_in[6];
    const float* lin_W    = (const float*)d_in[7];
    const float* lin_b    = (const float*)d_in[8];
    const float* W1       = (const float*)d_in[9];
    const float* b1       = (const float*)d_in[10];
    const float* W2       = (const float*)d_in[11];
    const float* b2       = (const float*)d_in[12];
    const float* edge_W   = (const float*)d_in[13];
    const float* edge_b   = (const float*)d_in[14];
    const float* motif_W  = (const float*)d_in[15];
    const float* motif_b  = (const float*)d_in[16];
    const float* nodec_W  = (const float*)d_in[17];
    const float* nodec_b  = (const float*)d_in[18];
    const float* bin_W    = (const float*)d_in[19];
    const float* bin_b    = (const float*)d_in[20];
    const int* src = eidx;
    const int* dst = eidx + NE;
    float* out = (float*)d_out;

    float *x0, *x1, *x2, *agg, *en, *elin, *proj, *Wcat, *bcat;
    cudaGetSymbolAddress((void**)&x0,   g_x0);
    cudaGetSymbolAddress((void**)&x1,   g_x1);
    cudaGetSymbolAddress((void**)&x2,   g_x2);
    cudaGetSymbolAddress((void**)&agg,  g_agg);
    cudaGetSymbolAddress((void**)&en,   g_en);
    cudaGetSymbolAddress((void**)&elin, g_elin);
    cudaGetSymbolAddress((void**)&proj, g_proj);
    cudaGetSymbolAddress((void**)&Wcat, g_Wcat);
    cudaGetSymbolAddress((void**)&bcat, g_bcat);

    constexpr int SM128 = smem_bytes(128);
    constexpr int SM116 = smem_bytes(116);
    constexpr int SM85  = smem_bytes(85);
    cudaFuncSetAttribute(gemm_k<128, true,  0>, cudaFuncAttributeMaxDynamicSharedMemorySize, SM128);
    cudaFuncSetAttribute(gemm_k<128, true,  3>, cudaFuncAttributeMaxDynamicSharedMemorySize, SM128);
    cudaFuncSetAttribute(gemm_k<128, true,  1>, cudaFuncAttributeMaxDynamicSharedMemorySize, SM128);
    cudaFuncSetAttribute(gemm_k<128, false, 1>, cudaFuncAttributeMaxDynamicSharedMemorySize, SM128);
    cudaFuncSetAttribute(gemm_k<116, false, 0>, cudaFuncAttributeMaxDynamicSharedMemorySize, SM116);
    cudaFuncSetAttribute(gemm_k<85,  false, 2>, cudaFuncAttributeMaxDynamicSharedMemorySize, SM85);

    const int n4 = NN * D / 4;

    // 1) pack output-head weights
    pack_k<<<cdiv(128 * 116, 256), 256>>>(edge_W, nodec_W, bin_W, edge_b, nodec_b, bin_b,
                                          Wcat, bcat);
    // 2) rel features: normalize 50 rows, then lin+relu -> elin[50,128]
    norm_gather_k<<<cdiv((long long)NRELS * 32, 256), 256>>>(rel_emb, nullptr, NRELS, en);
    gemm_k<128, true, 0><<<1, 256, SM128>>>(en, nullptr, nullptr, NRELS, lin_W, lin_b, elin);
    // 3) node features: fused gather + l2norm + lin + relu -> x0
    gemm_k<128, true, 3><<<cdiv(NN, 64), 256, SM128>>>(node_emb, nullptr, node_ids, NN,
                                                       lin_W, lin_b, x0);
    // 4) GINE layer 1
    zero_k<<<cdiv(n4, 256), 256>>>((float4*)agg, n4);
    msg_k<<<cdiv((long long)NE * 32, 256), 256>>>(x0, elin, src, dst, rel_ids, agg, NE);
    gemm_k<128, true, 1><<<cdiv(NN, 64), 256, SM128>>>(x0, agg, nullptr, NN, W1, b1, x1);
    // 5) GINE layer 2 (no relu)
    zero_k<<<cdiv(n4, 256), 256>>>((float4*)agg, n4);
    msg_k<<<cdiv((long long)NE * 32, 256), 256>>>(x1, elin, src, dst, rel_ids, agg, NE);
    gemm_k<128, false, 1><<<cdiv(NN, 64), 256, SM128>>>(x1, agg, nullptr, NN, W2, b2, x2);
    // 6) fused per-node projection: P1|P2|nodec|bin
    gemm_k<116, false, 0><<<cdiv(NN, 64), 256, SM116>>>(x2, nullptr, nullptr, NN,
                                                        Wcat, bcat, proj);
    // 7) outputs
    edge_out_k<<<cdiv((long long)NE * 25, 256), 256>>>(proj, src, dst, out);
    gemm_k<85, false, 2><<<cdiv(NCEN, 64), 256, SM85>>>(x2, nullptr, center, NCEN,
                                                        motif_W, motif_b, out + OFF_MOTIF);
    node_out_k<<<cdiv((long long)NMOLN * 15, 256), 256>>>(proj, nonmol, out + OFF_NODE);
    bin_out_k<<<cdiv(NN, 256), 256>>>(proj, out + OFF_BIN);
}

// round 3
// speedup vs baseline: 1.2143x; 1.0559x over previous
#include <cuda_runtime.h>
#include <cstdint>

// ---------------------------------------------------------------------------
// Problem constants
// ---------------------------------------------------------------------------
#define NN     100000
#define NE     600000
#define NCEN   512
#define NMOLN  20000
#define NRELS  50
#define D      128
#define NMOT   85

#define OFF_MOTIF (NE * 50)
#define OFF_NODE  (OFF_MOTIF + NCEN * NMOT)
#define OFF_BIN   (OFF_NODE + NMOLN * 15)

// ---------------------------------------------------------------------------
// Device scratch
// ---------------------------------------------------------------------------
__device__ float g_x0  [NN * D];
__device__ float g_x1  [NN * D];
__device__ float g_x2  [NN * D];
__device__ float g_agg [NN * D];
__device__ float g_en  [NRELS * D];
__device__ float g_elin[NRELS * D];
__device__ float g_proj[NN * 116];
__device__ float g_Wcat[D * 116];
__device__ float g_bcat[116];

// ---------------------------------------------------------------------------
// f32x2 packed-FMA helper
// ---------------------------------------------------------------------------
__device__ __forceinline__ void fma2(unsigned long long& acc, unsigned long long a,
                                     unsigned long long b) {
    asm("fma.rn.f32x2 %0, %1, %2, %0;" : "+l"(acc) : "l"(a), "l"(b));
}
__device__ __forceinline__ void upk2(unsigned long long v, float& lo, float& hi) {
    asm("mov.b64 {%0,%1}, %2;" : "=f"(lo), "=f"(hi) : "l"(v));
}

// ---------------------------------------------------------------------------
// Gather + L2-normalize (used only for the 50 relation rows)
// ---------------------------------------------------------------------------
__global__ void norm_gather_k(const float* __restrict__ table,
                              const int* __restrict__ ids, int n,
                              float* __restrict__ out) {
    int w = (blockIdx.x * blockDim.x + threadIdx.x) >> 5;
    if (w >= n) return;
    int lane = threadIdx.x & 31;
    int g = ids ? ids[w] : w;
    float4 v = reinterpret_cast<const float4*>(table + (size_t)g * D)[lane];
    float ss = v.x * v.x + v.y * v.y + v.z * v.z + v.w * v.w;
#pragma unroll
    for (int o = 16; o; o >>= 1) ss += __shfl_xor_sync(0xffffffffu, ss, o);
    float inv = 1.0f / fmaxf(sqrtf(ss), 1e-12f);
    v.x *= inv; v.y *= inv; v.z *= inv; v.w *= inv;
    reinterpret_cast<float4*>(out + (size_t)w * D)[lane] = v;
}

// ---------------------------------------------------------------------------
// Tiled GEMM with k-pair f32x2 packing.
// Y[r,c] = act( sum_k A[r,k]*W[k,c] + b[c] ),  K=128, C<=128.
// Block: 256 threads, tile 64 rows x 128 cols.
// Warp (wid): warprow=wid&1 (32 rows), warpcol=wid>>1 (32 cols).
// Lane: cg=lane&7 (col group), rg=lane>>3 (row group of 8).
// Thread: 8 rows x 4 cols {cA,cA+1,cB,cB+1}.
// Each acc is f32x2 holding (even-k sum, odd-k sum); halves added at the end.
// AMODE: 0=A1 ; 1=A1+A2 ; 2=A1[ridx[r]] ; 3=l2norm(A1[ridx[r]])
// ---------------------------------------------------------------------------
#define KK 64          // k-pairs
#define CS 128         // padded col count in sW2
#define PA 130         // sA row stride (floats), conflict-free

template <int C, bool RELU, int AMODE>
__global__ __launch_bounds__(256, 2)
void gemm_k(const float* __restrict__ A1, const float* __restrict__ A2,
            const int* __restrict__ ridx, int nrows,
            const float* __restrict__ W, const float* __restrict__ bias,
            float* __restrict__ Y) {
    extern __shared__ float sm[];
    float2* sW2 = (float2*)sm;                    // [KK][CS] float2 = 65536 B
    float*  sA  = sm + 2 * KK * CS;               // [64][PA]        = 33280 B
    float*  sB  = sA + 64 * PA;                   // [128]
    float*  sInv= sB + 128;                       // [64]
    int*    sIdx= (int*)(sInv + 64);              // [64]

    const int tid = threadIdx.x;

    // stage W as k-pairs: sW2[kk][c] = (W[2kk][c], W[2kk+1][c]); pad cols with 0
    for (int i = tid; i < KK * CS; i += 256) {
        int kk = i / CS, c = i - kk * CS;
        float2 v = make_float2(0.f, 0.f);
        if (c < C) { v.x = W[(2 * kk) * C + c]; v.y = W[(2 * kk + 1) * C + c]; }
        sW2[i] = v;
    }
    if (tid < 128) sB[tid] = (tid < C) ? bias[tid] : 0.0f;

    const int r0 = blockIdx.x * 64;
    if (AMODE >= 2) {
        if (tid < 64) {
            int gr = r0 + tid;
            sIdx[tid] = (gr < nrows) ? ridx[gr] : 0;
        }
        __syncthreads();
    }
    // stage A tile (64 x 128), padded stride
    for (int i = tid; i < 64 * 128; i += 256) {
        int r = i >> 7, k = i & 127;
        int gr = r0 + r;
        float v = 0.0f;
        if (gr < nrows) {
            if (AMODE == 0)      v = A1[(size_t)gr * D + k];
            else if (AMODE == 1) v = A1[(size_t)gr * D + k] + A2[(size_t)gr * D + k];
            else                 v = A1[(size_t)sIdx[r] * D + k];
        }
        sA[r * PA + k] = v;
    }
    __syncthreads();

    if (AMODE == 3) {
        int lane = tid & 31, w = tid >> 5;
#pragma unroll
        for (int rr = 0; rr < 8; rr++) {
            int r = w * 8 + rr;
            float s = 0.0f;
#pragma unroll
            for (int j = 0; j < 4; j++) {
                float a = sA[r * PA + lane + 32 * j];
                s += a * a;
            }
#pragma unroll
            for (int o = 16; o; o >>= 1) s += __shfl_xor_sync(0xffffffffu, s, o);
            if (lane == 0) sInv[r] = 1.0f / fmaxf(sqrtf(s), 1e-12f);
        }
        __syncthreads();
        for (int i = tid; i < 64 * 128; i += 256) {
            int r = i >> 7, k = i & 127;
            sA[r * PA + k] *= sInv[r];
        }
        __syncthreads();
    }

    const int lane = tid & 31, wid = tid >> 5;
    const int cg = lane & 7, rg = lane >> 3;
    const int warprow = wid & 1, warpcol = wid >> 1;
    const int rowb = warprow * 32 + rg * 8;       // thread's first tile row
    const int cA = warpcol * 32 + 2 * cg;         // col pair A
    const int cB = cA + 16;                       // col pair B

    unsigned long long acc[8][4];
#pragma unroll
    for (int r = 0; r < 8; r++)
#pragma unroll
        for (int j = 0; j < 4; j++) acc[r][j] = 0ull;

    const float* sAr = sA + rowb * PA;

#pragma unroll 4
    for (int kk = 0; kk < KK; kk++) {
        // w pairs for 4 cols: two LDS.128 (conflict-free phases)
        ulonglong2 wA = *reinterpret_cast<const ulonglong2*>(sW2 + kk * CS + cA);
        ulonglong2 wB = *reinterpret_cast<const ulonglong2*>(sW2 + kk * CS + cB);
#pragma unroll
        for (int r = 0; r < 8; r++) {
            unsigned long long ap =
                *reinterpret_cast<const unsigned long long*>(sAr + r * PA + 2 * kk);
            fma2(acc[r][0], ap, wA.x);
            fma2(acc[r][1], ap, wA.y);
            fma2(acc[r][2], ap, wB.x);
            fma2(acc[r][3], ap, wB.y);
        }
    }

#pragma unroll
    for (int r = 0; r < 8; r++) {
        int row = r0 + rowb + r;
        if (row >= nrows) continue;
        float* yr = Y + (size_t)row * C;
#pragma unroll
        for (int j = 0; j < 4; j++) {
            int c = (j < 2) ? (cA + j) : (cB + j - 2);
            if (c < C) {
                float lo, hi;
                upk2(acc[r][j], lo, hi);
                float v = lo + hi + sB[c];
                if (RELU) v = fmaxf(v, 0.0f);
                yr[c] = v;
            }
        }
    }
}

// ---------------------------------------------------------------------------
// Message pass: agg[dst] += relu(X[src] + Elin[rel]).  One warp per edge.
// ---------------------------------------------------------------------------
__global__ void msg_k(const float* __restrict__ X, const float* __restrict__ Elin,
                      const int* __restrict__ src, const int* __restrict__ dst,
                      const int* __restrict__ rel, float* __restrict__ agg, int nE) {
    int w = (blockIdx.x * blockDim.x + threadIdx.x) >> 5;
    if (w >= nE) return;
    int lane = threadIdx.x & 31;
    int s = __ldg(src + w), d = __ldg(dst + w), r = __ldg(rel + w);
    float4 a = reinterpret_cast<const float4*>(X + (size_t)s * D)[lane];
    float4 b = reinterpret_cast<const float4*>(Elin + (size_t)r * D)[lane];
    float4 m;
    m.x = fmaxf(a.x + b.x, 0.0f);
    m.y = fmaxf(a.y + b.y, 0.0f);
    m.z = fmaxf(a.z + b.z, 0.0f);
    m.w = fmaxf(a.w + b.w, 0.0f);
    atomicAdd(reinterpret_cast<float4*>(agg + (size_t)d * D) + lane, m);
}

__global__ void zero_k(float4* __restrict__ p, int n4) {
    int i = blockIdx.x * blockDim.x + threadIdx.x;
    if (i < n4) p[i] = make_float4(0.f, 0.f, 0.f, 0.f);
}

__global__ void pack_k(const float* __restrict__ eW, const float* __restrict__ ncW,
                       const float* __restrict__ bW, const float* __restrict__ eb,
                       const float* __restrict__ ncb, const float* __restrict__ bb,
                       float* __restrict__ Wcat, float* __restrict__ bcat) {
    int i = blockIdx.x * blockDim.x + threadIdx.x;
    if (i < 128 * 116) {
        int k = i / 116, c = i - k * 116;
        float v;
        if (c < 50)       v = eW[k * 50 + c];
        else if (c < 100) v = eW[(128 + k) * 50 + (c - 50)];
        else if (c < 115) v = ncW[k * 15 + (c - 100)];
        else              v = bW[k];
        Wcat[i] = v;
    }
    if (i < 116) {
        float v;
        if (i < 50)       v = eb[i];
        else if (i < 100) v = 0.0f;
        else if (i < 115) v = ncb[i - 100];
        else              v = bb[0];
        bcat[i] = v;
    }
}

__global__ void edge_out_k(const float* __restrict__ proj, const int* __restrict__ src,
                           const int* __restrict__ dst, float* __restrict__ out) {
    int i = blockIdx.x * blockDim.x + threadIdx.x;
    if (i >= NE * 25) return;
    int e = i / 25, j = i - e * 25;
    int c = j * 2;
    int s = __ldg(src + e), d = __ldg(dst + e);
    float2 p1 = *reinterpret_cast<const float2*>(proj + (size_t)s * 116 + c);
    float2 p2 = *reinterpret_cast<const float2*>(proj + (size_t)d * 116 + 50 + c);
    *reinterpret_cast<float2*>(out + (size_t)e * 50 + c) =
        make_float2(p1.x + p2.x, p1.y + p2.y);
}

__global__ void node_out_k(const float* __restrict__ proj, const int* __restrict__ ids,
                           float* __restrict__ out) {
    int i = blockIdx.x * blockDim.x + threadIdx.x;
    if (i >= NMOLN * 15) return;
    int m = i / 15, c = i - m * 15;
    out[i] = proj[(size_t)__ldg(ids + m) * 116 + 100 + c];
}

__global__ void bin_out_k(const float* __restrict__ proj, float* __restrict__ out) {
    int n = blockIdx.x * blockDim.x + threadIdx.x;
    if (n < NN) out[n] = proj[(size_t)n * 116 + 115];
}

// ---------------------------------------------------------------------------
// Launch
// ---------------------------------------------------------------------------
static inline int cdiv(long long a, long long b) { return (int)((a + b - 1) / b); }

// smem: sW2 + sA + sB + sInv + sIdx
static constexpr int SMEM_GEMM = (2 * KK * CS + 64 * PA + 128 + 64 + 64) * 4;

extern "C" void kernel_launch(void* const* d_in, const int* in_sizes, int n_in,
                              void* d_out, int out_size) {
    const int*   node_ids = (const int*)d_in[0];
    const int*   rel_ids  = (const int*)d_in[1];
    const int*   center   = (const int*)d_in[2];
    const int*   nonmol   = (const int*)d_in[3];
    const int*   eidx     = (const int*)d_in[4];
    const float* node_emb = (const float*)d_in[5];
    const float* rel_emb  = (const float*)d_in[6];
    const float* lin_W    = (const float*)d_in[7];
    const float* lin_b    = (const float*)d_in[8];
    const float* W1       = (const float*)d_in[9];
    const float* b1       = (const float*)d_in[10];
    const float* W2       = (const float*)d_in[11];
    const float* b2       = (const float*)d_in[12];
    const float* edge_W   = (const float*)d_in[13];
    const float* edge_b   = (const float*)d_in[14];
    const float* motif_W  = (const float*)d_in[15];
    const float* motif_b  = (const float*)d_in[16];
    const float* nodec_W  = (const float*)d_in[17];
    const float* nodec_b  = (const float*)d_in[18];
    const float* bin_W    = (const float*)d_in[19];
    const float* bin_b    = (const float*)d_in[20];
    const int* src = eidx;
    const int* dst = eidx + NE;
    float* out = (float*)d_out;

    float *x0, *x1, *x2, *agg, *en, *elin, *proj, *Wcat, *bcat;
    cudaGetSymbolAddress((void**)&x0,   g_x0);
    cudaGetSymbolAddress((void**)&x1,   g_x1);
    cudaGetSymbolAddress((void**)&x2,   g_x2);
    cudaGetSymbolAddress((void**)&agg,  g_agg);
    cudaGetSymbolAddress((void**)&en,   g_en);
    cudaGetSymbolAddress((void**)&elin, g_elin);
    cudaGetSymbolAddress((void**)&proj, g_proj);
    cudaGetSymbolAddress((void**)&Wcat, g_Wcat);
    cudaGetSymbolAddress((void**)&bcat, g_bcat);

    cudaFuncSetAttribute(gemm_k<128, true,  0>, cudaFuncAttributeMaxDynamicSharedMemorySize, SMEM_GEMM);
    cudaFuncSetAttribute(gemm_k<128, true,  3>, cudaFuncAttributeMaxDynamicSharedMemorySize, SMEM_GEMM);
    cudaFuncSetAttribute(gemm_k<128, true,  1>, cudaFuncAttributeMaxDynamicSharedMemorySize, SMEM_GEMM);
    cudaFuncSetAttribute(gemm_k<128, false, 1>, cudaFuncAttributeMaxDynamicSharedMemorySize, SMEM_GEMM);
    cudaFuncSetAttribute(gemm_k<116, false, 0>, cudaFuncAttributeMaxDynamicSharedMemorySize, SMEM_GEMM);
    cudaFuncSetAttribute(gemm_k<85,  false, 2>, cudaFuncAttributeMaxDynamicSharedMemorySize, SMEM_GEMM);

    const int n4 = NN * D / 4;

    // 1) pack output-head weights
    pack_k<<<cdiv(128 * 116, 256), 256>>>(edge_W, nodec_W, bin_W, edge_b, nodec_b, bin_b,
                                          Wcat, bcat);
    // 2) rel features
    norm_gather_k<<<cdiv((long long)NRELS * 32, 256), 256>>>(rel_emb, nullptr, NRELS, en);
    gemm_k<128, true, 0><<<1, 256, SMEM_GEMM>>>(en, nullptr, nullptr, NRELS, lin_W, lin_b, elin);
    // 3) node features: fused gather + l2norm + lin + relu -> x0
    gemm_k<128, true, 3><<<cdiv(NN, 64), 256, SMEM_GEMM>>>(node_emb, nullptr, node_ids, NN,
                                                           lin_W, lin_b, x0);
    // 4) GINE layer 1
    zero_k<<<cdiv(n4, 256), 256>>>((float4*)agg, n4);
    msg_k<<<cdiv((long long)NE * 32, 256), 256>>>(x0, elin, src, dst, rel_ids, agg, NE);
    gemm_k<128, true, 1><<<cdiv(NN, 64), 256, SMEM_GEMM>>>(x0, agg, nullptr, NN, W1, b1, x1);
    // 5) GINE layer 2
    zero_k<<<cdiv(n4, 256), 256>>>((float4*)agg, n4);
    msg_k<<<cdiv((long long)NE * 32, 256), 256>>>(x1, elin, src, dst, rel_ids, agg, NE);
    gemm_k<128, false, 1><<<cdiv(NN, 64), 256, SMEM_GEMM>>>(x1, agg, nullptr, NN, W2, b2, x2);
    // 6) fused projection
    gemm_k<116, false, 0><<<cdiv(NN, 64), 256, SMEM_GEMM>>>(x2, nullptr, nullptr, NN,
                                                            Wcat, bcat, proj);
    // 7) outputs
    edge_out_k<<<cdiv((long long)NE * 25, 256), 256>>>(proj, src, dst, out);
    gemm_k<85, false, 2><<<cdiv(NCEN, 64), 256, SMEM_GEMM>>>(x2, nullptr, center, NCEN,
                                                             motif_W, motif_b, out + OFF_MOTIF);
    node_out_k<<<cdiv((long long)NMOLN * 15, 256), 256>>>(proj, nonmol, out + OFF_NODE);
    bin_out_k<<<cdiv(NN, 256), 256>>>(proj, out + OFF_BIN);
}

// round 7
// speedup vs baseline: 1.3791x; 1.1357x over previous
#include <cuda_runtime.h>
#include <cuda_bf16.h>
#include <cstdint>

// ---------------------------------------------------------------------------
// Problem constants
// ---------------------------------------------------------------------------
#define NN     100000
#define NE     600000
#define NCEN   512
#define NMOLN  20000
#define NRELS  50
#define D      128
#define NMOT   85

#define OFF_MOTIF (NE * 50)
#define OFF_NODE  (OFF_MOTIF + NCEN * NMOT)
#define OFF_BIN   (OFF_NODE + NMOLN * 15)

// ---------------------------------------------------------------------------
// Device scratch
// ---------------------------------------------------------------------------
__device__ float g_x0  [NN * D];
__device__ float g_x1  [NN * D];
__device__ float g_x2  [NN * D];
__device__ float g_agg [NN * D];
__device__ float g_en  [NRELS * D];
__device__ float g_elin[NRELS * D];
__device__ float g_proj[NN * 116];
__device__ float g_Wcat[D * 116];
__device__ float g_bcat[116];

// ---------------------------------------------------------------------------
// bf16 helpers
// ---------------------------------------------------------------------------
__device__ __forceinline__ uint32_t pack_bf2(float a, float b) {
    __nv_bfloat162 h(__float2bfloat16_rn(a), __float2bfloat16_rn(b));
    return *reinterpret_cast<uint32_t*>(&h);
}
__device__ __forceinline__ float bf_hi(float a) {
    return __bfloat162float(__float2bfloat16_rn(a));
}

// mma.sync m16n8k16 row.col f32.bf16.bf16.f32
#define MMA_BF16(c, a, b0, b1) \
    asm volatile("mma.sync.aligned.m16n8k16.row.col.f32.bf16.bf16.f32 " \
        "{%0,%1,%2,%3}, {%4,%5,%6,%7}, {%8,%9}, {%0,%1,%2,%3};" \
        : "+f"((c)[0]), "+f"((c)[1]), "+f"((c)[2]), "+f"((c)[3]) \
        : "r"((a)[0]), "r"((a)[1]), "r"((a)[2]), "r"((a)[3]), \
          "r"(b0), "r"(b1))

// ---------------------------------------------------------------------------
// HMMA GEMM: Y[r,c] = act( sum_k A[r,k]*W[k,c] + b[c] ),  K=128, C<=128.
// 3-term bf16 split (ah*bh + ah*bl + al*bh) ~ fp32 accuracy.
// CTA: 256 thr = 8 warps (4 row-warps x 2 col-warps), tile 128x128.
// Warp: 32 rows x 64 cols = 2 x 8 m16n8k16 tiles.
// SMEM rows have stride PK=68 words (conflict-free fragment loads).
// AMODE: 0 = A1 ; 1 = A1+A2 ; 2 = A1[ridx[r]] ; 3 = l2norm(A1[ridx[r]])
// For AMODE==3, a temporary fp32 row buffer overlays the (not-yet-staged)
// B region of smem; B staging happens after the A pack with a sync between.
// ---------------------------------------------------------------------------
#define PK 68   // b32 words per staged row (64 data + 4 pad)
#define PF 132  // fp32 scratch row stride for AMODE==3

template <int C, bool RELU, int AMODE>
__global__ __launch_bounds__(256, 1)
void hgemm_k(const float* __restrict__ A1, const float* __restrict__ A2,
             const int* __restrict__ ridx, int nrows,
             const float* __restrict__ W, const float* __restrict__ bias,
             float* __restrict__ Y) {
    extern __shared__ __align__(16) uint32_t sm32[];
    uint32_t* sAh = sm32;                  // [128][PK]
    uint32_t* sAl = sAh + 128 * PK;
    uint32_t* sBh = sAl + 128 * PK;        // [n][PK] = W^T packed k-pairs
    uint32_t* sBl = sBh + 128 * PK;
    float*  sBias = (float*)(sBl + 128 * PK);   // 128
    int*    sIdx  = (int*)(sBias + 128);        // 128
    float*  sNrm  = (float*)(sIdx + 128);       // 128

    const int tid = threadIdx.x;
    const int r0 = blockIdx.x * 128;

    if (tid < 128) sBias[tid] = (tid < C) ? bias[tid] : 0.0f;
    if (AMODE >= 2) {
        if (tid < 128) {
            int gr = r0 + tid;
            sIdx[tid] = (gr < nrows) ? ridx[gr] : 0;
        }
        __syncthreads();
    }

    if (AMODE == 3) {
        // ---- fused gather + l2norm staging ----
        float* sF = (float*)sBh;   // overlay: [128][PF] fp32 (written before B)
        for (int i = tid; i < 128 * 32; i += 256) {
            int r = i >> 5, j = i & 31;
            int gr = r0 + r;
            float4 v = make_float4(0.f, 0.f, 0.f, 0.f);
            if (gr < nrows)
                v = reinterpret_cast<const float4*>(A1 + (size_t)sIdx[r] * D)[j];
            *reinterpret_cast<float4*>(sF + r * PF + 4 * j) = v;
        }
        __syncthreads();
        {
            int lane = tid & 31, w = tid >> 5;
#pragma unroll
            for (int rr = 0; rr < 16; rr++) {
                int r = w * 16 + rr;
                float s = 0.f;
#pragma unroll
                for (int j = 0; j < 4; j++) {
                    float a = sF[r * PF + lane + 32 * j];
                    s += a * a;
                }
#pragma unroll
                for (int o = 16; o; o >>= 1) s += __shfl_xor_sync(0xffffffffu, s, o);
                if (lane == 0) sNrm[r] = 1.0f / fmaxf(sqrtf(s), 1e-12f);
            }
        }
        __syncthreads();
        for (int i = tid; i < 128 * 32; i += 256) {
            int r = i >> 5, j = i & 31;
            float inv = sNrm[r];
            float4 v = *reinterpret_cast<float4*>(sF + r * PF + 4 * j);
            v.x *= inv; v.y *= inv; v.z *= inv; v.w *= inv;
            uint2 hh, ll;
            hh.x = pack_bf2(v.x, v.y);
            hh.y = pack_bf2(v.z, v.w);
            ll.x = pack_bf2(v.x - bf_hi(v.x), v.y - bf_hi(v.y));
            ll.y = pack_bf2(v.z - bf_hi(v.z), v.w - bf_hi(v.w));
            *reinterpret_cast<uint2*>(sAh + r * PK + 2 * j) = hh;
            *reinterpret_cast<uint2*>(sAl + r * PK + 2 * j) = ll;
        }
        __syncthreads();   // protect sF region before B staging overwrites it
    } else {
        // ---- stage A (hi/lo): 128 rows x 32 float4 ----
        for (int i = tid; i < 128 * 32; i += 256) {
            int r = i >> 5, j = i & 31;
            int gr = r0 + r;
            float4 v = make_float4(0.f, 0.f, 0.f, 0.f);
            if (gr < nrows) {
                if (AMODE == 0) {
                    v = reinterpret_cast<const float4*>(A1 + (size_t)gr * D)[j];
                } else if (AMODE == 1) {
                    float4 a = reinterpret_cast<const float4*>(A1 + (size_t)gr * D)[j];
                    float4 b = reinterpret_cast<const float4*>(A2 + (size_t)gr * D)[j];
                    v = make_float4(a.x + b.x, a.y + b.y, a.z + b.z, a.w + b.w);
                } else {
                    v = reinterpret_cast<const float4*>(A1 + (size_t)sIdx[r] * D)[j];
                }
            }
            uint2 hh, ll;
            hh.x = pack_bf2(v.x, v.y);
            hh.y = pack_bf2(v.z, v.w);
            ll.x = pack_bf2(v.x - bf_hi(v.x), v.y - bf_hi(v.y));
            ll.y = pack_bf2(v.z - bf_hi(v.z), v.w - bf_hi(v.w));
            *reinterpret_cast<uint2*>(sAh + r * PK + 2 * j) = hh;
            *reinterpret_cast<uint2*>(sAl + r * PK + 2 * j) = ll;
        }
    }

    // ---- stage B = W^T (hi/lo): sB[n][kp] = (W[2kp][n], W[2kp+1][n]) ----
    for (int i = tid; i < 64 * 128; i += 256) {
        int kp = i >> 7, n = i & 127;   // coalesced along n
        float w0 = 0.f, w1 = 0.f;
        if (n < C) {
            w0 = W[(2 * kp) * C + n];
            w1 = W[(2 * kp + 1) * C + n];
        }
        sBh[n * PK + kp] = pack_bf2(w0, w1);
        sBl[n * PK + kp] = pack_bf2(w0 - bf_hi(w0), w1 - bf_hi(w1));
    }
    __syncthreads();

    // ---- mainloop ----
    const int lane = tid & 31, wid = tid >> 5;
    const int g = lane >> 2, tg = lane & 3;
    const int wm = wid & 3, wn = wid >> 2;

    float acc[2][8][4];
#pragma unroll
    for (int mt = 0; mt < 2; mt++)
#pragma unroll
        for (int nt = 0; nt < 8; nt++)
#pragma unroll
            for (int j = 0; j < 4; j++) acc[mt][nt][j] = 0.f;

    const uint32_t* pA = sAh + (wm * 32 + g) * PK;   // sAl = pA + 128*PK
    const uint32_t* pB = sBh + (wn * 64 + g) * PK;   // sBl = pB + 128*PK

#pragma unroll
    for (int ks = 0; ks < 8; ks++) {
        const int kb = ks * 8 + tg;
        uint32_t ah[2][4], al[2][4];
#pragma unroll
        for (int mt = 0; mt < 2; mt++) {
            const uint32_t* ba = pA + mt * 16 * PK;
            ah[mt][0] = ba[kb];
            ah[mt][1] = ba[8 * PK + kb];
            ah[mt][2] = ba[kb + 4];
            ah[mt][3] = ba[8 * PK + kb + 4];
            const uint32_t* bl_ = ba + 128 * PK;
            al[mt][0] = bl_[kb];
            al[mt][1] = bl_[8 * PK + kb];
            al[mt][2] = bl_[kb + 4];
            al[mt][3] = bl_[8 * PK + kb + 4];
        }
#pragma unroll
        for (int nt = 0; nt < 8; nt++) {
            const uint32_t* bb = pB + nt * 8 * PK;
            uint32_t bh0 = bb[kb], bh1 = bb[kb + 4];
            uint32_t bl0 = bb[128 * PK + kb], bl1 = bb[128 * PK + kb + 4];
#pragma unroll
            for (int mt = 0; mt < 2; mt++) {
                MMA_BF16(acc[mt][nt], ah[mt], bh0, bh1);
                MMA_BF16(acc[mt][nt], ah[mt], bl0, bl1);
                MMA_BF16(acc[mt][nt], al[mt], bh0, bh1);
            }
        }
    }

    // ---- epilogue: direct global stores (float2 only when C even) ----
#pragma unroll
    for (int mt = 0; mt < 2; mt++) {
#pragma unroll
        for (int nt = 0; nt < 8; nt++) {
            int col = wn * 64 + nt * 8 + tg * 2;
            if (col >= C) continue;
            float b0 = sBias[col];
            float b1 = (col + 1 < C) ? sBias[col + 1] : 0.f;
#pragma unroll
            for (int h = 0; h < 2; h++) {
                int row = r0 + wm * 32 + mt * 16 + g + h * 8;
                if (row >= nrows) continue;
                float v0 = acc[mt][nt][2 * h + 0] + b0;
                float v1 = acc[mt][nt][2 * h + 1] + b1;
                if (RELU) { v0 = fmaxf(v0, 0.f); v1 = fmaxf(v1, 0.f); }
                float* yr = Y + (size_t)row * C + col;
                if ((C & 1) == 0 && col + 1 < C) {
                    *reinterpret_cast<float2*>(yr) = make_float2(v0, v1);
                } else {
                    yr[0] = v0;
                    if (col + 1 < C) yr[1] = v1;
                }
            }
        }
    }
}

static constexpr int SMEM_HGEMM = (4 * 128 * PK) * 4 + 512 + 512 + 512;

// ---------------------------------------------------------------------------
// Gather + L2-normalize rows (one warp per row). ids==nullptr -> identity.
// (only used for the 50 relation rows)
// ---------------------------------------------------------------------------
__global__ void norm_gather_k(const float* __restrict__ table,
                              const int* __restrict__ ids, int n,
                              float* __restrict__ out) {
    int w = (blockIdx.x * blockDim.x + threadIdx.x) >> 5;
    if (w >= n) return;
    int lane = threadIdx.x & 31;
    int g = ids ? ids[w] : w;
    float4 v = reinterpret_cast<const float4*>(table + (size_t)g * D)[lane];
    float ss = v.x * v.x + v.y * v.y + v.z * v.z + v.w * v.w;
#pragma unroll
    for (int o = 16; o; o >>= 1) ss += __shfl_xor_sync(0xffffffffu, ss, o);
    float inv = 1.0f / fmaxf(sqrtf(ss), 1e-12f);
    v.x *= inv; v.y *= inv; v.z *= inv; v.w *= inv;
    reinterpret_cast<float4*>(out + (size_t)w * D)[lane] = v;
}

// ---------------------------------------------------------------------------
// Message pass: agg[dst] += relu(X[src] + Elin[rel]).  One warp per edge.
// ---------------------------------------------------------------------------
__global__ void msg_k(const float* __restrict__ X, const float* __restrict__ Elin,
                      const int* __restrict__ src, const int* __restrict__ dst,
                      const int* __restrict__ rel, float* __restrict__ agg, int nE) {
    int w = (blockIdx.x * blockDim.x + threadIdx.x) >> 5;
    if (w >= nE) return;
    int lane = threadIdx.x & 31;
    int s = __ldg(src + w), d = __ldg(dst + w), r = __ldg(rel + w);
    float4 a = reinterpret_cast<const float4*>(X + (size_t)s * D)[lane];
    float4 b = reinterpret_cast<const float4*>(Elin + (size_t)r * D)[lane];
    float4 m;
    m.x = fmaxf(a.x + b.x, 0.0f);
    m.y = fmaxf(a.y + b.y, 0.0f);
    m.z = fmaxf(a.z + b.z, 0.0f);
    m.w = fmaxf(a.w + b.w, 0.0f);
    atomicAdd(reinterpret_cast<float4*>(agg + (size_t)d * D) + lane, m);
}

__global__ void zero_k(float4* __restrict__ p, int n4) {
    int i = blockIdx.x * blockDim.x + threadIdx.x;
    if (i < n4) p[i] = make_float4(0.f, 0.f, 0.f, 0.f);
}

__global__ void pack_k(const float* __restrict__ eW, const float* __restrict__ ncW,
                       const float* __restrict__ bW, const float* __restrict__ eb,
                       const float* __restrict__ ncb, const float* __restrict__ bb,
                       float* __restrict__ Wcat, float* __restrict__ bcat) {
    int i = blockIdx.x * blockDim.x + threadIdx.x;
    if (i < 128 * 116) {
        int k = i / 116, c = i - k * 116;
        float v;
        if (c < 50)       v = eW[k * 50 + c];
        else if (c < 100) v = eW[(128 + k) * 50 + (c - 50)];
        else if (c < 115) v = ncW[k * 15 + (c - 100)];
        else              v = bW[k];
        Wcat[i] = v;
    }
    if (i < 116) {
        float v;
        if (i < 50)       v = eb[i];
        else if (i < 100) v = 0.0f;
        else if (i < 115) v = ncb[i - 100];
        else              v = bb[0];
        bcat[i] = v;
    }
}

__global__ void edge_out_k(const float* __restrict__ proj, const int* __restrict__ src,
                           const int* __restrict__ dst, float* __restrict__ out) {
    int i = blockIdx.x * blockDim.x + threadIdx.x;
    if (i >= NE * 25) return;
    int e = i / 25, j = i - e * 25;
    int c = j * 2;
    int s = __ldg(src + e), d = __ldg(dst + e);
    float2 p1 = *reinterpret_cast<const float2*>(proj + (size_t)s * 116 + c);
    float2 p2 = *reinterpret_cast<const float2*>(proj + (size_t)d * 116 + 50 + c);
    *reinterpret_cast<float2*>(out + (size_t)e * 50 + c) =
        make_float2(p1.x + p2.x, p1.y + p2.y);
}

__global__ void node_out_k(const float* __restrict__ proj, const int* __restrict__ ids,
                           float* __restrict__ out) {
    int i = blockIdx.x * blockDim.x + threadIdx.x;
    if (i >= NMOLN * 15) return;
    int m = i / 15, c = i - m * 15;
    out[i] = proj[(size_t)__ldg(ids + m) * 116 + 100 + c];
}

__global__ void bin_out_k(const float* __restrict__ proj, float* __restrict__ out) {
    int n = blockIdx.x * blockDim.x + threadIdx.x;
    if (n < NN) out[n] = proj[(size_t)n * 116 + 115];
}

// ---------------------------------------------------------------------------
// Launch
// ---------------------------------------------------------------------------
static inline int cdiv(long long a, long long b) { return (int)((a + b - 1) / b); }

extern "C" void kernel_launch(void* const* d_in, const int* in_sizes, int n_in,
                              void* d_out, int out_size) {
    const int*   node_ids = (const int*)d_in[0];
    const int*   rel_ids  = (const int*)d_in[1];
    const int*   center   = (const int*)d_in[2];
    const int*   nonmol   = (const int*)d_in[3];
    const int*   eidx     = (const int*)d_in[4];
    const float* node_emb = (const float*)d_in[5];
    const float* rel_emb  = (const float*)d_in[6];
    const float* lin_W    = (const float*)d_in[7];
    const float* lin_b    = (const float*)d_in[8];
    const float* W1       = (const float*)d_in[9];
    const float* b1       = (const float*)d_in[10];
    const float* W2       = (const float*)d_in[11];
    const float* b2       = (const float*)d_in[12];
    const float* edge_W   = (const float*)d_in[13];
    const float* edge_b   = (const float*)d_in[14];
    const float* motif_W  = (const float*)d_in[15];
    const float* motif_b  = (const float*)d_in[16];
    const float* nodec_W  = (const float*)d_in[17];
    const float* nodec_b  = (const float*)d_in[18];
    const float* bin_W    = (const float*)d_in[19];
    const float* bin_b    = (const float*)d_in[20];
    const int* src = eidx;
    const int* dst = eidx + NE;
    float* out = (float*)d_out;

    float *x0, *x1, *x2, *agg, *en, *elin, *proj, *Wcat, *bcat;
    cudaGetSymbolAddress((void**)&x0,   g_x0);
    cudaGetSymbolAddress((void**)&x1,   g_x1);
    cudaGetSymbolAddress((void**)&x2,   g_x2);
    cudaGetSymbolAddress((void**)&agg,  g_agg);
    cudaGetSymbolAddress((void**)&en,   g_en);
    cudaGetSymbolAddress((void**)&elin, g_elin);
    cudaGetSymbolAddress((void**)&proj, g_proj);
    cudaGetSymbolAddress((void**)&Wcat, g_Wcat);
    cudaGetSymbolAddress((void**)&bcat, g_bcat);

    cudaFuncSetAttribute(hgemm_k<128, true,  0>, cudaFuncAttributeMaxDynamicSharedMemorySize, SMEM_HGEMM);
    cudaFuncSetAttribute(hgemm_k<128, true,  3>, cudaFuncAttributeMaxDynamicSharedMemorySize, SMEM_HGEMM);
    cudaFuncSetAttribute(hgemm_k<128, true,  1>, cudaFuncAttributeMaxDynamicSharedMemorySize, SMEM_HGEMM);
    cudaFuncSetAttribute(hgemm_k<128, false, 1>, cudaFuncAttributeMaxDynamicSharedMemorySize, SMEM_HGEMM);
    cudaFuncSetAttribute(hgemm_k<116, false, 0>, cudaFuncAttributeMaxDynamicSharedMemorySize, SMEM_HGEMM);
    cudaFuncSetAttribute(hgemm_k<85,  false, 2>, cudaFuncAttributeMaxDynamicSharedMemorySize, SMEM_HGEMM);

    const int n4 = NN * D / 4;
    const int gN = cdiv(NN, 128);

    // 1) pack output-head weights
    pack_k<<<cdiv(128 * 116, 256), 256>>>(edge_W, nodec_W, bin_W, edge_b, nodec_b, bin_b,
                                          Wcat, bcat);
    // 2) rel features
    norm_gather_k<<<cdiv((long long)NRELS * 32, 256), 256>>>(rel_emb, nullptr, NRELS, en);
    hgemm_k<128, true, 0><<<1, 256, SMEM_HGEMM>>>(en, nullptr, nullptr, NRELS,
                                                  lin_W, lin_b, elin);
    // 3) node features: fused gather + l2norm + lin + relu -> x0
    hgemm_k<128, true, 3><<<gN, 256, SMEM_HGEMM>>>(node_emb, nullptr, node_ids, NN,
                                                   lin_W, lin_b, x0);
    // 4) GINE layer 1
    zero_k<<<cdiv(n4, 256), 256>>>((float4*)agg, n4);
    msg_k<<<cdiv((long long)NE * 32, 256), 256>>>(x0, elin, src, dst, rel_ids, agg, NE);
    hgemm_k<128, true, 1><<<gN, 256, SMEM_HGEMM>>>(x0, agg, nullptr, NN, W1, b1, x1);
    // 5) GINE layer 2
    zero_k<<<cdiv(n4, 256), 256>>>((float4*)agg, n4);
    msg_k<<<cdiv((long long)NE * 32, 256), 256>>>(x1, elin, src, dst, rel_ids, agg, NE);
    hgemm_k<128, false, 1><<<gN, 256, SMEM_HGEMM>>>(x1, agg, nullptr, NN, W2, b2, x2);
    // 6) fused projection
    hgemm_k<116, false, 0><<<gN, 256, SMEM_HGEMM>>>(x2, nullptr, nullptr, NN,
                                                    Wcat, bcat, proj);
    // 7) outputs
    edge_out_k<<<cdiv((long long)NE * 25, 256), 256>>>(proj, src, dst, out);
    hgemm_k<85, false, 2><<<cdiv(NCEN, 128), 256, SMEM_HGEMM>>>(x2, nullptr, center, NCEN,
                                                                motif_W, motif_b,
                                                                out + OFF_MOTIF);
    node_out_k<<<cdiv((long long)NMOLN * 15, 256), 256>>>(proj, nonmol, out + OFF_NODE);
    bin_out_k<<<cdiv(NN, 256), 256>>>(proj, out + OFF_BIN);
}